// round 7
// baseline (speedup 1.0000x reference)
#include <cuda_runtime.h>

// FFF (fast feedforward) sparse tree-walk kernel, round 7.
// Inputs (metadata order):
//   d_in[0]: oldx  [8192, 768]  float32
//   d_in[1]: w_in  [4095, 768]  float32
//   d_in[2]: w_out [768, 4095]  float32
// Output: [8192, 768] float32
//
// Round-7: TWO full-warp tokens interleaved per warp. While token A is in its
// shuffle-reduce dead window, token B's loads/FMAs issue. Zero extra traffic,
// full coalescing, 2x chain ILP. Lane-distributed logits + single gelu kept.

#define FFF_B       8192
#define FFF_D       768
#define FFF_NODES   4095
#define FFF_DEPTH   11
#define FFF_LEVELS  (FFF_DEPTH + 1)      // 12 nodes on the path
#define FFF_ROW4    (FFF_D / 4)          // 192 float4 per 768-float row

// Transposed w_out scratch: [FFF_NODES, FFF_D] (node-major, coalesced rows).
__device__ float g_wout_t[(size_t)FFF_NODES * FFF_D];

// ---------------------------------------------------------------------------
// Tiled transpose: w_out [768, 4095] -> g_wout_t [4095, 768]
// ---------------------------------------------------------------------------
__global__ void fff_transpose_wout(const float* __restrict__ w_out) {
    __shared__ float tile[32][33];
    const int n0 = blockIdx.x * 32;   // node dim (4095)
    const int o0 = blockIdx.y * 32;   // output dim (768)

    const int n = n0 + threadIdx.x;
    #pragma unroll
    for (int j = 0; j < 4; j++) {
        const int o = o0 + threadIdx.y + j * 8;     // o < 768 always
        if (n < FFF_NODES) {
            tile[threadIdx.y + j * 8][threadIdx.x] = w_out[(size_t)o * FFF_NODES + n];
        }
    }
    __syncthreads();

    const int oo = o0 + threadIdx.x;                // always < 768
    #pragma unroll
    for (int j = 0; j < 4; j++) {
        const int nn = n0 + threadIdx.y + j * 8;
        if (nn < FFF_NODES) {
            g_wout_t[(size_t)nn * FFF_D + oo] = tile[threadIdx.x][threadIdx.y + j * 8];
        }
    }
}

__device__ __forceinline__ float fff_warp_sum(float v) {
    #pragma unroll
    for (int off = 16; off > 0; off >>= 1)
        v += __shfl_xor_sync(0xffffffffu, v, off);
    return v;
}

// ---------------------------------------------------------------------------
// Main kernel: one warp handles TWO tokens with interleaved serial chains.
// Phase 1: dual decision walk; lane d keeps logit d of each token.
// Phase 2: per chunk, 12+12 independent gathered w_out loads (MLP=24).
// ---------------------------------------------------------------------------
__global__ void __launch_bounds__(256, 3)
fff_walk_kernel(const float* __restrict__ x,
                const float* __restrict__ w_in,
                float* __restrict__ out) {
    const int warp = (int)((blockIdx.x * blockDim.x + threadIdx.x) >> 5);
    const int lane = threadIdx.x & 31;
    const int tokA = warp * 2;
    const int tokB = warp * 2 + 1;

    const float4* __restrict__ wi4 = reinterpret_cast<const float4*>(w_in);
    const float4* __restrict__ wo4 = reinterpret_cast<const float4*>(g_wout_t);
    const float4* __restrict__ xA4 = reinterpret_cast<const float4*>(x) + (size_t)tokA * FFF_ROW4;
    const float4* __restrict__ xB4 = reinterpret_cast<const float4*>(x) + (size_t)tokB * FFF_ROW4;

    // Both tokens' x rows: 6 float4 per lane each, lane-interleaved.
    float4 xvA[6], xvB[6];
    #pragma unroll
    for (int i = 0; i < 6; i++) { xvA[i] = xA4[i * 32 + lane]; xvB[i] = xB4[i * 32 + lane]; }

    // ---------------- Phase 1: dual serial decision walk ----------------
    float mylA = 0.f, mylB = 0.f;      // lane d holds level-d logit of each token
    unsigned curA = 0, curB = 0;
    #pragma unroll
    for (int d = 0; d < FFF_LEVELS; d++) {
        const float4* __restrict__ wrA = wi4 + (size_t)curA * FFF_ROW4;
        const float4* __restrict__ wrB = wi4 + (size_t)curB * FFF_ROW4;
        float pA0 = 0.f, pA1 = 0.f, pA2 = 0.f, pA3 = 0.f;
        float pB0 = 0.f, pB1 = 0.f, pB2 = 0.f, pB3 = 0.f;
        #pragma unroll
        for (int i = 0; i < 6; i++) {
            const float4 a = wrA[i * 32 + lane];
            const float4 b = wrB[i * 32 + lane];
            pA0 = fmaf(a.x, xvA[i].x, pA0);
            pA1 = fmaf(a.y, xvA[i].y, pA1);
            pA2 = fmaf(a.z, xvA[i].z, pA2);
            pA3 = fmaf(a.w, xvA[i].w, pA3);
            pB0 = fmaf(b.x, xvB[i].x, pB0);
            pB1 = fmaf(b.y, xvB[i].y, pB1);
            pB2 = fmaf(b.z, xvB[i].z, pB2);
            pB3 = fmaf(b.w, xvB[i].w, pB3);
        }
        // Two independent reduce chains — shuffle latencies overlap.
        float vA = (pA0 + pA1) + (pA2 + pA3);
        float vB = (pB0 + pB1) + (pB2 + pB3);
        #pragma unroll
        for (int off = 16; off > 0; off >>= 1) {
            vA += __shfl_xor_sync(0xffffffffu, vA, off);
            vB += __shfl_xor_sync(0xffffffffu, vB, off);
        }
        if (lane == d) { mylA = vA; mylB = vB; }
        curA = 2u * curA + 1u + (vA > 0.0f ? 1u : 0u);
        curB = 2u * curB + 1u + (vB > 0.0f ? 1u : 0u);
    }
    const unsigned vfA = curA + 1u;    // level-12 virtual node + 1
    const unsigned vfB = curB + 1u;

    // ---- ONE exact-erf gelu per token (lane d -> act d) ----
    const float actA = 0.5f * mylA * (1.0f + erff(mylA * 0.70710678118654752440f));
    const float actB = 0.5f * mylB * (1.0f + erff(mylB * 0.70710678118654752440f));

    // ---------------- Phase 2: dual independent accumulation ----------------
    float4* __restrict__ oA4 = reinterpret_cast<float4*>(out) + (size_t)tokA * FFF_ROW4;
    float4* __restrict__ oB4 = reinterpret_cast<float4*>(out) + (size_t)tokB * FFF_ROW4;
    #pragma unroll
    for (int i = 0; i < 6; i++) {
        const unsigned chunk = (unsigned)(i * 32 + lane);
        float aA0 = 0.f, aA1 = 0.f, aA2 = 0.f, aA3 = 0.f;
        float aB0 = 0.f, aB1 = 0.f, aB2 = 0.f, aB3 = 0.f;
        #pragma unroll
        for (int d = 0; d < FFF_LEVELS; d++) {
            const unsigned nodeA = (vfA >> (FFF_LEVELS - d)) - 1u;
            const unsigned nodeB = (vfB >> (FFF_LEVELS - d)) - 1u;
            const float adA = __shfl_sync(0xffffffffu, actA, d);
            const float adB = __shfl_sync(0xffffffffu, actB, d);
            const float4 wA = wo4[nodeA * (unsigned)FFF_ROW4 + chunk];
            const float4 wB = wo4[nodeB * (unsigned)FFF_ROW4 + chunk];
            aA0 = fmaf(adA, wA.x, aA0);
            aA1 = fmaf(adA, wA.y, aA1);
            aA2 = fmaf(adA, wA.z, aA2);
            aA3 = fmaf(adA, wA.w, aA3);
            aB0 = fmaf(adB, wB.x, aB0);
            aB1 = fmaf(adB, wB.y, aB1);
            aB2 = fmaf(adB, wB.z, aB2);
            aB3 = fmaf(adB, wB.w, aB3);
        }
        oA4[chunk] = make_float4(aA0, aA1, aA2, aA3);
        oB4[chunk] = make_float4(aB0, aB1, aB2, aB3);
    }
}

extern "C" void kernel_launch(void* const* d_in, const int* in_sizes, int n_in,
                              void* d_out, int out_size) {
    const float* x     = (const float*)d_in[0];
    const float* w_in  = (const float*)d_in[1];
    const float* w_out = (const float*)d_in[2];
    float* out = (float*)d_out;

    // 1) Transpose w_out into node-major scratch (coalesced both sides).
    {
        dim3 block(32, 8);
        dim3 grid((FFF_NODES + 31) / 32, FFF_D / 32);
        fff_transpose_wout<<<grid, block>>>(w_out);
    }

    // 2) Sparse tree walk: 2 tokens per warp, 8 warps per 256-thread block.
    {
        const int threads = 256;
        const int blocks = (FFF_B / 2) / 8;   // 512 blocks
        fff_walk_kernel<<<blocks, threads>>>(x, w_in, out);
    }
}

// round 8
// speedup vs baseline: 1.2371x; 1.2371x over previous
#include <cuda_runtime.h>

// FFF (fast feedforward) sparse tree-walk, round 8: two-kernel split.
// Inputs (metadata order):
//   d_in[0]: oldx  [8192, 768]  float32
//   d_in[1]: w_in  [4095, 768]  float32
//   d_in[2]: w_out [768, 4095]  float32
// Output: [8192, 768] float32
//
//   k1: transpose w_out -> node-major scratch
//   k2: decide  — serial tree walk per warp-token, writes acts[12] + leaf
//   k3: accum   — 6 warps/token, MLP=12 gathered accumulation at L1 bandwidth

#define FFF_B       8192
#define FFF_D       768
#define FFF_NODES   4095
#define FFF_DEPTH   11
#define FFF_LEVELS  (FFF_DEPTH + 1)      // 12 nodes on the path
#define FFF_ROW4    (FFF_D / 4)          // 192 float4 per 768-float row

// Scratch: transposed w_out (node-major), per-token activations + leaf.
__device__ float    g_wout_t[(size_t)FFF_NODES * FFF_D];
__device__ float    g_acts[(size_t)FFF_B * FFF_LEVELS];
__device__ unsigned g_leaf[FFF_B];

// ---------------------------------------------------------------------------
// k1: tiled transpose w_out [768, 4095] -> g_wout_t [4095, 768]
// ---------------------------------------------------------------------------
__global__ void fff_transpose_wout(const float* __restrict__ w_out) {
    __shared__ float tile[32][33];
    const int n0 = blockIdx.x * 32;   // node dim (4095)
    const int o0 = blockIdx.y * 32;   // output dim (768)

    const int n = n0 + threadIdx.x;
    #pragma unroll
    for (int j = 0; j < 4; j++) {
        const int o = o0 + threadIdx.y + j * 8;     // o < 768 always
        if (n < FFF_NODES) {
            tile[threadIdx.y + j * 8][threadIdx.x] = w_out[(size_t)o * FFF_NODES + n];
        }
    }
    __syncthreads();

    const int oo = o0 + threadIdx.x;                // always < 768
    #pragma unroll
    for (int j = 0; j < 4; j++) {
        const int nn = n0 + threadIdx.y + j * 8;
        if (nn < FFF_NODES) {
            g_wout_t[(size_t)nn * FFF_D + oo] = tile[threadIdx.x][threadIdx.y + j * 8];
        }
    }
}

__device__ __forceinline__ float fff_warp_sum(float v) {
    #pragma unroll
    for (int off = 16; off > 0; off >>= 1)
        v += __shfl_xor_sync(0xffffffffu, v, off);
    return v;
}

// ---------------------------------------------------------------------------
// k2: decide — one warp per token. Serial decision walk; lane d keeps the
// level-d logit; one gelu; writes acts + leaf to scratch.
// ---------------------------------------------------------------------------
__global__ void __launch_bounds__(256, 4)
fff_decide_kernel(const float* __restrict__ x,
                  const float* __restrict__ w_in) {
    const int warp = (int)((blockIdx.x * blockDim.x + threadIdx.x) >> 5);
    const int lane = threadIdx.x & 31;

    const float4* __restrict__ x4  = reinterpret_cast<const float4*>(x) + (size_t)warp * FFF_ROW4;
    const float4* __restrict__ wi4 = reinterpret_cast<const float4*>(w_in);

    // Token's x row: 6 float4 per lane, lane-interleaved (coalesced).
    float4 xv[6];
    #pragma unroll
    for (int i = 0; i < 6; i++) xv[i] = x4[i * 32 + lane];

    float mylogit = 0.f;   // lane d holds the level-d logit
    unsigned cur = 0;
    #pragma unroll
    for (int d = 0; d < FFF_LEVELS; d++) {
        const float4* __restrict__ wr = wi4 + (size_t)cur * FFF_ROW4;
        float p0 = 0.f, p1 = 0.f, p2 = 0.f, p3 = 0.f;
        #pragma unroll
        for (int i = 0; i < 6; i += 2) {
            const float4 a = wr[i * 32 + lane];
            const float4 b = wr[(i + 1) * 32 + lane];
            p0 = fmaf(a.x, xv[i].x, p0);
            p1 = fmaf(a.y, xv[i].y, p1);
            p2 = fmaf(a.z, xv[i].z, p2);
            p3 = fmaf(a.w, xv[i].w, p3);
            p0 = fmaf(b.x, xv[i + 1].x, p0);
            p1 = fmaf(b.y, xv[i + 1].y, p1);
            p2 = fmaf(b.z, xv[i + 1].z, p2);
            p3 = fmaf(b.w, xv[i + 1].w, p3);
        }
        const float p = fff_warp_sum((p0 + p1) + (p2 + p3));
        if (lane == d) mylogit = p;
        cur = 2u * cur + 1u + (p > 0.0f ? 1u : 0u);
    }

    // ONE exact-erf gelu (matches jax.nn.gelu approximate=False); lane d -> act d.
    const float myact = 0.5f * mylogit *
                        (1.0f + erff(mylogit * 0.70710678118654752440f));

    if (lane < FFF_LEVELS) g_acts[(size_t)warp * FFF_LEVELS + lane] = myact;
    if (lane == 0)         g_leaf[warp] = cur + 1u;   // level-12 virtual node + 1
}

// ---------------------------------------------------------------------------
// k3: accum — one warp per 512B output chunk (6 warps per token, 49152 warps).
// 12 independent gathered float4 loads per warp (MLP=12), no serial chain.
// ---------------------------------------------------------------------------
__global__ void __launch_bounds__(256, 8)
fff_accum_kernel(float* __restrict__ out) {
    const int gwarp = (int)((blockIdx.x * blockDim.x + threadIdx.x) >> 5);
    const int lane  = threadIdx.x & 31;
    const int tok   = gwarp / 6;                       // 192 chunks = 6 warps/token
    const unsigned chunk = (unsigned)((gwarp % 6) * 32 + lane);

    const float4* __restrict__ wo4 = reinterpret_cast<const float4*>(g_wout_t);
    const unsigned vf = g_leaf[tok];

    float acts[FFF_LEVELS];
    #pragma unroll
    for (int d = 0; d < FFF_LEVELS; d++)
        acts[d] = g_acts[(size_t)tok * FFF_LEVELS + d];   // uniform broadcast loads

    float a0 = 0.f, a1 = 0.f, a2 = 0.f, a3 = 0.f;
    #pragma unroll
    for (int d = 0; d < FFF_LEVELS; d++) {
        const unsigned node = (vf >> (FFF_LEVELS - d)) - 1u;
        const float4 w = wo4[node * (unsigned)FFF_ROW4 + chunk];  // independent gathers
        a0 = fmaf(acts[d], w.x, a0);
        a1 = fmaf(acts[d], w.y, a1);
        a2 = fmaf(acts[d], w.z, a2);
        a3 = fmaf(acts[d], w.w, a3);
    }

    float4* __restrict__ o4 = reinterpret_cast<float4*>(out) + (size_t)tok * FFF_ROW4;
    o4[chunk] = make_float4(a0, a1, a2, a3);
}

extern "C" void kernel_launch(void* const* d_in, const int* in_sizes, int n_in,
                              void* d_out, int out_size) {
    const float* x     = (const float*)d_in[0];
    const float* w_in  = (const float*)d_in[1];
    const float* w_out = (const float*)d_in[2];
    float* out = (float*)d_out;

    // k1: transpose w_out into node-major scratch.
    {
        dim3 block(32, 8);
        dim3 grid((FFF_NODES + 31) / 32, FFF_D / 32);
        fff_transpose_wout<<<grid, block>>>(w_out);
    }

    // k2: decision walk — one warp per token, 8 warps per 256-thread block.
    {
        const int threads = 256;
        const int blocks = FFF_B / 8;                  // 1024 blocks
        fff_decide_kernel<<<blocks, threads>>>(x, w_in);
    }

    // k3: accumulation — 6 warps per token, 8 warps per block.
    {
        const int threads = 256;
        const int total_warps = FFF_B * 6;             // 49152
        const int blocks = total_warps / 8;            // 6144 blocks
        fff_accum_kernel<<<blocks, threads>>>(out);
    }
}